// round 14
// baseline (speedup 1.0000x reference)
#include <cuda_runtime.h>
#include <cstdint>

#define BB 32
#define NN 16384
#define DD 64

// Scratch (no allocations allowed)
__device__ uint32_t g_keys[BB * NN];             // 2MB monotonic keys
__device__ float    g_rowsum[BB];
__device__ int      g_k[BB];
__device__ unsigned g_visbits[BB * (NN / 32)];   // 64KB visibility bitmask
__device__ unsigned g_flag[BB];                  // per-row "visibility ready"
__device__ unsigned g_done;

// ---------------------------------------------------------------------------
// k_keys: full-chip key computation, 2 elems/thread, accurate logf (proven
// bit-exact visible set). Also resets all inter-kernel state for this launch.
// ---------------------------------------------------------------------------
__global__ void __launch_bounds__(256) k_keys(
    const float* __restrict__ u_g, const float* __restrict__ lpt,
    const float* __restrict__ lph, const float* __restrict__ lpw)
{
    int tid2 = blockIdx.x * 256 + threadIdx.x;
    if (tid2 < BB) { g_rowsum[tid2] = 0.f; g_flag[tid2] = 0u; }
    if (tid2 == 0) g_done = 0u;
    int idx = tid2 * 2;
    int b = idx >> 14;
    int n = idx & (NN - 1);
    int t = n >> 10;
    int h = (n >> 5) & 31;
    int w = n & 31;                          // even; w,w+1 share t/h

    float2 u = *(const float2*)(u_g + idx);
    float2 lw = *(const float2*)(lpw + b * 32 + w);
    float base = lpt[b * 16 + t] + lph[b * 32 + h];

    float g0 = -logf(-logf(u.x));
    float g1 = -logf(-logf(u.y));
    float ws0 = g0 + (base + lw.x);          // (lpt+lph)+lpw == ref association
    float ws1 = g1 + (base + lw.y);
    uint32_t b0 = __float_as_uint(ws0);
    uint32_t b1 = __float_as_uint(ws1);
    uint2 outk;
    outk.x = (b0 & 0x80000000u) ? ~b0 : (b0 | 0x80000000u);
    outk.y = (b1 & 0x80000000u) ? ~b1 : (b1 | 0x80000000u);
    *(uint2*)(g_keys + idx) = outk;
}

// ---------------------------------------------------------------------------
// k_select_mask: ONE kernel, two roles by blockIdx.
//   CTAs 0..31   : exact radix select for row b (keys staged in smem),
//                  emit visibility bitmask, publish g_flag[b].
//   CTAs 32..543 : gather CTAs (16 per row, 4 chunks of 256 tokens each);
//                  spin on their row's flag, then masked float4 gather,
//                  visible-float writes, rowsum atomics; last emits loss.
// Select CTAs are bids 0..31 -> guaranteed wave-1 resident => no deadlock.
// ---------------------------------------------------------------------------
__global__ void __launch_bounds__(1024, 2) k_select_mask(
    const float* __restrict__ u_k, const float* __restrict__ score,
    float* __restrict__ out, int out_size)
{
    extern __shared__ uint32_t skeys[];       // 16384 words (64KB)
    __shared__ unsigned hist[256];
    __shared__ unsigned suf[256];
    __shared__ uint32_t s_prefix;
    __shared__ int s_krem, s_eqcnt;
    __shared__ float ssum[32];
    __shared__ bool slast;

    int tid = threadIdx.x;

    if (blockIdx.x < BB) {
        // ================= SELECT ROLE =================
        int b = blockIdx.x;

        float r = u_k[0] + (float)b * (1.0f / 31.0f);
        r = r - floorf(r);
        int k = (int)(16384.0f * r);
        k = k < 1 ? 1 : (k > NN - 1 ? NN - 1 : k);
        if (tid == 0) g_k[b] = k;

        const uint32_t* __restrict__ keys = g_keys + ((size_t)b << 14);
        #pragma unroll
        for (int s = 0; s < 16; s++)
            skeys[s * 1024 + tid] = keys[s * 1024 + tid];
        __syncthreads();

        uint32_t prefix = 0, pmask = 0;
        int krem = k;
        for (int pass = 0; pass < 4; pass++) {
            int shift = 24 - 8 * pass;
            if (tid < 256) hist[tid] = 0;
            __syncthreads();
            #pragma unroll
            for (int s = 0; s < 16; s++) {
                uint32_t kk = skeys[s * 1024 + tid];
                if ((kk & pmask) == prefix)
                    atomicAdd(&hist[(kk >> shift) & 255u], 1u);
            }
            __syncthreads();
            if (tid < 256) suf[tid] = hist[tid];
            __syncthreads();
            for (int d = 1; d < 256; d <<= 1) {   // inclusive suffix sums
                unsigned v = 0;
                if (tid < 256) { v = suf[tid]; if (tid + d < 256) v += suf[tid + d]; }
                __syncthreads();
                if (tid < 256) suf[tid] = v;
                __syncthreads();
            }
            if (tid < 256) {
                int above = (int)(suf[tid] - hist[tid]);
                if (above < krem && krem <= (int)suf[tid]) {
                    s_prefix = prefix | ((uint32_t)tid << shift);
                    s_krem = krem - above;
                    if (pass == 3) s_eqcnt = (int)hist[tid];
                }
            }
            __syncthreads();
            prefix = s_prefix;
            krem = s_krem;
            pmask |= (0xFFu << shift);
            __syncthreads();
        }

        uint32_t thr = prefix;
        int eqcnt = s_eqcnt;

        #pragma unroll
        for (int s = 0; s < 16; s++) {
            uint32_t kk = skeys[s * 1024 + tid];
            bool vis;
            if (kk > thr) vis = true;
            else if (kk < thr) vis = false;
            else if (eqcnt <= krem) vis = true;   // all ties fit in top-k
            else {
                // rare tie path: stable rank by index among equals
                int n = s * 1024 + tid;
                int cnt = 0;
                for (int i = 0; i < n; i++) cnt += (skeys[i] == thr);
                vis = cnt < krem;
            }
            unsigned m = __ballot_sync(0xffffffffu, vis);
            if ((tid & 31) == 0)
                g_visbits[(b << 9) + ((s * 1024 + tid) >> 5)] = m;
        }
        // publish
        __syncthreads();
        __threadfence();
        if (tid == 0) atomicExch(&g_flag[b], 1u);
    } else {
        // ================= GATHER ROLE =================
        int i = blockIdx.x - BB;                  // 0..511
        int rrow = i & 31;
        int cs = i >> 5;                          // 0..15
        int w = tid >> 5, lane = tid & 31;
        int chunk = cs * 4 + (w >> 3);            // 0..63
        int tok0 = (rrow << 14) + chunk * 256 + (w & 7) * 32;

        if (tid == 0) {
            while (atomicAdd(&g_flag[rrow], 0u) == 0u) { }
        }
        __syncthreads();
        __threadfence();

        unsigned visword = g_visbits[tok0 >> 5];

        if (out_size >= BB * NN) {
            int off = (out_size > BB * NN) ? 1 : 0;   // loss slot first
            out[off + tok0 + lane] = ((visword >> lane) & 1u) ? 1.0f : 0.0f;
        }

        int sub = lane >> 4;
        const float4* __restrict__ rowsq =
            (const float4*)score + (((size_t)(tok0 + sub)) << 4) + (lane & 15);

        float a0 = 0.f, a1 = 0.f, a2 = 0.f, a3 = 0.f;
        #pragma unroll
        for (int jj = 0; jj < 16; jj += 4) {
            float4 z = make_float4(0.f, 0.f, 0.f, 0.f);
            float4 v0 = z, v1 = z, v2 = z, v3 = z;
            if (!((visword >> (2 * (jj + 0) + sub)) & 1u)) v0 = rowsq[(jj + 0) * 32];
            if (!((visword >> (2 * (jj + 1) + sub)) & 1u)) v1 = rowsq[(jj + 1) * 32];
            if (!((visword >> (2 * (jj + 2) + sub)) & 1u)) v2 = rowsq[(jj + 2) * 32];
            if (!((visword >> (2 * (jj + 3) + sub)) & 1u)) v3 = rowsq[(jj + 3) * 32];
            a0 += (v0.x + v0.y) + (v0.z + v0.w);
            a1 += (v1.x + v1.y) + (v1.z + v1.w);
            a2 += (v2.x + v2.y) + (v2.z + v2.w);
            a3 += (v3.x + v3.y) + (v3.z + v3.w);
        }
        float acc = (a0 + a1) + (a2 + a3);
        #pragma unroll
        for (int o = 16; o; o >>= 1) acc += __shfl_down_sync(0xffffffffu, acc, o);
        if (lane == 0) ssum[w] = acc;
        __syncthreads();
        if (tid == 0) {
            float t = 0.f;
            #pragma unroll
            for (int j = 0; j < 32; j++) t += ssum[j];
            atomicAdd(&g_rowsum[rrow], t);
            __threadfence();
            unsigned old = atomicAdd(&g_done, 1u);
            slast = (old == 511u);
        }
        __syncthreads();
        if (slast && tid < 32) {
            __threadfence();
            float v = g_rowsum[tid] * (16384.0f / (float)(NN - g_k[tid]));
            #pragma unroll
            for (int o = 16; o; o >>= 1) v += __shfl_down_sync(0xffffffffu, v, o);
            if (tid == 0 && out_size != BB * NN)
                out[0] = v / 33554432.0f;             // B*N*D
        }
    }
}

extern "C" void kernel_launch(void* const* d_in, const int* in_sizes, int n_in,
                              void* d_out, int out_size) {
    const float* u_g   = (const float*)d_in[0];
    const float* lpt   = (const float*)d_in[1];
    const float* lph   = (const float*)d_in[2];
    const float* lpw   = (const float*)d_in[3];
    const float* u_k   = (const float*)d_in[4];
    const float* score = (const float*)d_in[5];
    float* out = (float*)d_out;

    cudaFuncSetAttribute(k_select_mask,
                         cudaFuncAttributeMaxDynamicSharedMemorySize, 65536);

    k_keys<<<BB * NN / 512, 256>>>(u_g, lpt, lph, lpw);
    k_select_mask<<<BB + 512, 1024, 65536>>>(u_k, score, out, out_size);
}

// round 15
// speedup vs baseline: 1.1616x; 1.1616x over previous
#include <cuda_runtime.h>
#include <cstdint>

#define BB 32
#define NN 16384
#define DD 64

// Scratch (no allocations allowed)
__device__ uint32_t g_keys[BB * NN];             // 2MB monotonic keys
__device__ float    g_rowsum[BB];
__device__ int      g_k[BB];
__device__ unsigned g_visbits[BB * (NN / 32)];   // 64KB visibility bitmask
__device__ unsigned g_done;

// ---------------------------------------------------------------------------
// k_keys: full-chip key computation, 2 elems/thread, accurate logf.
// ---------------------------------------------------------------------------
__global__ void __launch_bounds__(256) k_keys(
    const float* __restrict__ u_g, const float* __restrict__ lpt,
    const float* __restrict__ lph, const float* __restrict__ lpw)
{
    int tid2 = blockIdx.x * 256 + threadIdx.x;
    if (tid2 < BB) g_rowsum[tid2] = 0.f;
    if (tid2 == 0) g_done = 0u;
    int idx = tid2 * 2;
    int b = idx >> 14;
    int n = idx & (NN - 1);
    int t = n >> 10;
    int h = (n >> 5) & 31;
    int w = n & 31;                          // even; w,w+1 share t/h

    float2 u = *(const float2*)(u_g + idx);
    float2 lw = *(const float2*)(lpw + b * 32 + w);
    float base = lpt[b * 16 + t] + lph[b * 32 + h];

    float g0 = -logf(-logf(u.x));
    float g1 = -logf(-logf(u.y));
    float ws0 = g0 + (base + lw.x);          // (lpt+lph)+lpw == ref association
    float ws1 = g1 + (base + lw.y);
    uint32_t b0 = __float_as_uint(ws0);
    uint32_t b1 = __float_as_uint(ws1);
    uint2 outk;
    outk.x = (b0 & 0x80000000u) ? ~b0 : (b0 | 0x80000000u);
    outk.y = (b1 & 0x80000000u) ? ~b1 : (b1 | 0x80000000u);
    *(uint2*)(g_keys + idx) = outk;
}

// ---------------------------------------------------------------------------
// k_select: one CTA per row; register keys + smem shadow; exact 4x8-bit
// radix select. Suffix sums via ONE warp (shfl scan) -> 2 barriers/pass
// instead of ~18. Emits visibility bitmask.
// ---------------------------------------------------------------------------
__global__ void __launch_bounds__(1024, 1) k_select(const float* __restrict__ u_k)
{
    extern __shared__ uint32_t skeys[];   // NN words (64KB)
    __shared__ unsigned hist[256];
    __shared__ unsigned suf[256];
    __shared__ uint32_t s_prefix;
    __shared__ int s_krem, s_eqcnt;

    int b = blockIdx.x;
    int tid = threadIdx.x;

    // k per row: rates = (u_k + b/31) % 1 ; k = clip(int(N*rates), 1, N-1)
    float r = u_k[0] + (float)b * (1.0f / 31.0f);
    r = r - floorf(r);
    int k = (int)(16384.0f * r);
    k = k < 1 ? 1 : (k > NN - 1 ? NN - 1 : k);
    if (tid == 0) g_k[b] = k;

    const uint32_t* __restrict__ keys = g_keys + ((size_t)b << 14);
    uint32_t key[16];
    #pragma unroll
    for (int s = 0; s < 16; s++) {
        uint32_t kk = keys[s * 1024 + tid];
        key[s] = kk;
        skeys[s * 1024 + tid] = kk;
    }
    if (tid < 256) hist[tid] = 0;
    __syncthreads();

    uint32_t prefix = 0, pmask = 0;
    int krem = k;
    for (int pass = 0; pass < 4; pass++) {
        int shift = 24 - 8 * pass;
        #pragma unroll
        for (int s = 0; s < 16; s++) {
            uint32_t kk = key[s];
            if ((kk & pmask) == prefix)
                atomicAdd(&hist[(kk >> shift) & 255u], 1u);
        }
        __syncthreads();

        // Single-warp suffix scan over 256 bins (8 bins/lane + shfl scan).
        if (tid < 32) {
            int base = tid * 8;
            unsigned gtot = 0;
            #pragma unroll
            for (int j = 0; j < 8; j++) gtot += hist[base + j];
            // inclusive suffix scan of group totals across lanes
            unsigned upper = gtot;
            #pragma unroll
            for (int o = 1; o < 32; o <<= 1) {
                unsigned t2 = __shfl_down_sync(0xffffffffu, upper, o);
                if (tid + o < 32) upper += t2;
            }
            unsigned run = upper - gtot;          // sum of groups > tid
            #pragma unroll
            for (int j = 7; j >= 0; j--) {
                run += hist[base + j];
                suf[base + j] = run;
            }
        }
        __syncthreads();

        if (tid < 256) {
            int above = (int)(suf[tid] - hist[tid]);   // strictly larger keys
            if (above < krem && krem <= (int)suf[tid]) {
                s_prefix = prefix | ((uint32_t)tid << shift);
                s_krem = krem - above;
                if (pass == 3) s_eqcnt = (int)hist[tid];
            }
        }
        __syncthreads();
        prefix = s_prefix;
        krem = s_krem;
        pmask |= (0xFFu << shift);
        if (tid < 256) hist[tid] = 0;              // reset for next pass
        __syncthreads();
    }

    uint32_t thr = prefix;
    int eqcnt = s_eqcnt;

    // Visibility -> bitmask (one ballot word per 32 consecutive tokens)
    #pragma unroll
    for (int s = 0; s < 16; s++) {
        uint32_t kk = key[s];
        bool vis;
        if (kk > thr) vis = true;
        else if (kk < thr) vis = false;
        else if (eqcnt <= krem) vis = true;          // all ties fit in top-k
        else {
            // rare tie path: stable rank by index among equals (from smem)
            int n = s * 1024 + tid;
            int cnt = 0;
            for (int i = 0; i < n; i++) cnt += (skeys[i] == thr);
            vis = cnt < krem;
        }
        unsigned m = __ballot_sync(0xffffffffu, vis);
        if ((tid & 31) == 0)
            g_visbits[(b << 9) + ((s * 1024 + tid) >> 5)] = m;
    }
}

// ---------------------------------------------------------------------------
// k_mask_final: half-warp float4 predicated gather (best measured shape),
// blocks round-robin over rows, last block emits the loss.
// ---------------------------------------------------------------------------
__global__ void __launch_bounds__(256) k_mask_final(
    const float* __restrict__ score, float* __restrict__ out, int out_size)
{
    __shared__ float ssum[8];
    __shared__ bool slast;
    int g = blockIdx.x;
    int b = g & 31;
    int chunk = g >> 5;
    int warp = threadIdx.x >> 5, lane = threadIdx.x & 31;
    int tok0 = (b << 14) + chunk * 256 + warp * 32;

    unsigned visword = g_visbits[tok0 >> 5];

    if (out_size >= BB * NN) {
        int off = (out_size > BB * NN) ? 1 : 0;      // loss slot first
        out[off + tok0 + lane] = ((visword >> lane) & 1u) ? 1.0f : 0.0f;
    }

    int sub = lane >> 4;
    const float4* __restrict__ rowsq =
        (const float4*)score + (((size_t)(tok0 + sub)) << 4) + (lane & 15);

    float a0 = 0.f, a1 = 0.f, a2 = 0.f, a3 = 0.f;
    #pragma unroll
    for (int jj = 0; jj < 16; jj += 4) {
        float4 z = make_float4(0.f, 0.f, 0.f, 0.f);
        float4 v0 = z, v1 = z, v2 = z, v3 = z;
        if (!((visword >> (2 * (jj + 0) + sub)) & 1u)) v0 = rowsq[(jj + 0) * 32];
        if (!((visword >> (2 * (jj + 1) + sub)) & 1u)) v1 = rowsq[(jj + 1) * 32];
        if (!((visword >> (2 * (jj + 2) + sub)) & 1u)) v2 = rowsq[(jj + 2) * 32];
        if (!((visword >> (2 * (jj + 3) + sub)) & 1u)) v3 = rowsq[(jj + 3) * 32];
        a0 += (v0.x + v0.y) + (v0.z + v0.w);
        a1 += (v1.x + v1.y) + (v1.z + v1.w);
        a2 += (v2.x + v2.y) + (v2.z + v2.w);
        a3 += (v3.x + v3.y) + (v3.z + v3.w);
    }
    float acc = (a0 + a1) + (a2 + a3);
    #pragma unroll
    for (int o = 16; o; o >>= 1) acc += __shfl_down_sync(0xffffffffu, acc, o);
    if (lane == 0) ssum[warp] = acc;
    __syncthreads();
    if (threadIdx.x == 0) {
        float t = 0.f;
        #pragma unroll
        for (int i = 0; i < 8; i++) t += ssum[i];
        atomicAdd(&g_rowsum[b], t);
        __threadfence();
        unsigned old = atomicAdd(&g_done, 1u);
        slast = (old == gridDim.x - 1);
    }
    __syncthreads();
    if (slast && threadIdx.x < 32) {
        __threadfence();
        float w = g_rowsum[threadIdx.x] *
                  (16384.0f / (float)(NN - g_k[threadIdx.x]));
        #pragma unroll
        for (int o = 16; o; o >>= 1) w += __shfl_down_sync(0xffffffffu, w, o);
        if (threadIdx.x == 0 && out_size != BB * NN)
            out[0] = w / 33554432.0f;                // B*N*D
    }
}

extern "C" void kernel_launch(void* const* d_in, const int* in_sizes, int n_in,
                              void* d_out, int out_size) {
    const float* u_g   = (const float*)d_in[0];
    const float* lpt   = (const float*)d_in[1];
    const float* lph   = (const float*)d_in[2];
    const float* lpw   = (const float*)d_in[3];
    const float* u_k   = (const float*)d_in[4];
    const float* score = (const float*)d_in[5];
    float* out = (float*)d_out;

    cudaFuncSetAttribute(k_select,
                         cudaFuncAttributeMaxDynamicSharedMemorySize, 65536);

    k_keys<<<BB * NN / 512, 256>>>(u_g, lpt, lph, lpw);
    k_select<<<BB, 1024, 65536>>>(u_k);
    k_mask_final<<<BB * NN / 256, 256>>>(score, out, out_size);
}